// round 16
// baseline (speedup 1.0000x reference)
#include <cuda_runtime.h>
#include <cuda_fp16.h>
#include <cstdint>

#define Bc 8
#define Tc 2048
#define Cc 1024
#define Hc 64
// (1/sqrt(1024)) * log2(e)  — folded into Q so softmax uses pure 2^x
#define QSCALE 0.045084220027840225f

// fp16 scratch
__device__ __half g_Qh[Bc * Tc * Hc];
__device__ __half g_Kh[Bc * Tc * Hc];
__device__ __half g_Vh[Bc * Tc * Hc];
__device__ __half g_Wth[3 * Hc * Cc];   // W transposed: [m][n][k]
// split-K partials (every element rewritten each launch — no zeroing needed)
__device__ float g_Po[2][Bc * Tc * Hc];
__device__ float g_Pl[2][Bc * Tc];

// ---------------------------------------------------------------------------
// helpers (generic PTX only: sm_80-class instructions)
// ---------------------------------------------------------------------------
__device__ __forceinline__ uint32_t smem_u32(const void* p) {
    uint32_t a;
    asm("{ .reg .u64 t; cvta.to.shared.u64 t, %1; cvt.u32.u64 %0, t; }" : "=r"(a) : "l"(p));
    return a;
}

__device__ __forceinline__ void ldsm_x4(uint32_t& r0, uint32_t& r1, uint32_t& r2,
                                        uint32_t& r3, uint32_t a) {
    asm volatile("ldmatrix.sync.aligned.m8n8.x4.shared.b16 {%0,%1,%2,%3}, [%4];"
                 : "=r"(r0), "=r"(r1), "=r"(r2), "=r"(r3) : "r"(a));
}
__device__ __forceinline__ void ldsm_x4_t(uint32_t& r0, uint32_t& r1, uint32_t& r2,
                                          uint32_t& r3, uint32_t a) {
    asm volatile("ldmatrix.sync.aligned.m8n8.x4.trans.shared.b16 {%0,%1,%2,%3}, [%4];"
                 : "=r"(r0), "=r"(r1), "=r"(r2), "=r"(r3) : "r"(a));
}

__device__ __forceinline__ void mma16816(float* d, const uint32_t* a,
                                         const uint32_t* b) {
    asm volatile(
        "mma.sync.aligned.m16n8k16.row.col.f32.f16.f16.f32 "
        "{%0,%1,%2,%3}, {%4,%5,%6,%7}, {%8,%9}, {%0,%1,%2,%3};"
        : "+f"(d[0]), "+f"(d[1]), "+f"(d[2]), "+f"(d[3])
        : "r"(a[0]), "r"(a[1]), "r"(a[2]), "r"(a[3]), "r"(b[0]), "r"(b[1]));
}

#define CP16(dst, src) asm volatile("cp.async.ca.shared.global [%0], [%1], 16;" :: "r"(dst), "l"(src))
#define CP_COMMIT()    asm volatile("cp.async.commit_group;" ::: "memory")
#define CP_WAIT0()     asm volatile("cp.async.wait_group 0;" ::: "memory")
#define CP_WAIT1()     asm volatile("cp.async.wait_group 1;" ::: "memory")

// swizzled byte offset in a [rows][64 halfs] fp16 tile (pitch 128B, 16B chunks)
__device__ __forceinline__ uint32_t swz(int row, int c8) {
    return (uint32_t)(row * 128 + ((c8 ^ (row & 7)) << 4));
}

// fast 2^y via FFMA pipe (no MUFU). |y| < 2^21, rel err ~4e-5.
__device__ __forceinline__ float fexp2(float y) {
    float t = y + 12582912.0f;                  // 1.5 * 2^23 (round-to-nearest int)
    int   n = __float_as_int(t) - 0x4B400000;
    float f = y - (t - 12582912.0f);            // f in [-0.5, 0.5]
    float u = f * 0.6931471805599453f;
    float p = 1.0f + u * (1.0f + u * (0.5f + u * (0.16666667f + u * 0.041666668f)));
    return __int_as_float(__float_as_int(p) + (n << 23));
}

// ---------------------------------------------------------------------------
// prep: W [1024,64] fp32 -> Wt [3][64][1024] fp16 (coalesced float4 reads)
// ---------------------------------------------------------------------------
__global__ __launch_bounds__(256) void prep_W(const float* __restrict__ Wq,
                                              const float* __restrict__ Wk,
                                              const float* __restrict__ Wv)
{
    int j = blockIdx.x * 256 + threadIdx.x;     // float4 index
    int m = j >> 14, f = j & 16383;
    int k = f >> 4, n4 = (f & 15) << 2;
    const float* W = (m == 0) ? Wq : (m == 1) ? Wk : Wv;
    float4 v = *(const float4*)&W[(size_t)k * Hc + n4];
    __half* dst = g_Wth + (size_t)m * 65536 + (size_t)n4 * Cc + k;
    dst[0]        = __float2half(v.x);
    dst[Cc]       = __float2half(v.y);
    dst[2 * Cc]   = __float2half(v.z);
    dst[3 * Cc]   = __float2half(v.w);
}

// ---------------------------------------------------------------------------
// proj: fused QKV.  CTA = 64 rows x (3 x 64) cols, 256 threads (8 warps:
// 4 row-groups x 2 col-groups of 96 output cols).  grid 256 -> 2 CTAs/SM:
// co-resident CTAs interleave the DRAM-load and tensor-MMA phases.
// K loop: 16 chunks of 64, double buffered.
// smem: XS[2] 8KB + WS[2] 24KB = 64KB dynamic.   (R4 proj, correctness-proven)
// ---------------------------------------------------------------------------
__global__ __launch_bounds__(256) void proj_kernel(const float* __restrict__ x)
{
    extern __shared__ __align__(128) char S[];
    const uint32_t sb = smem_u32(S);

    const int tid = threadIdx.x;
    const int wid = tid >> 5, lane = tid & 31;
    const int rg = wid & 3;          // row group: rows 16*rg
    const int cg = wid >> 2;         // col group: output cols 96*cg..96*cg+95
    const int rowbase = blockIdx.x * 64;

    auto xs_base = [&](int buf) { return (uint32_t)(buf * 8192); };
    auto ws_base = [&](int buf) { return (uint32_t)(16384 + buf * 24576); };

    float4 xr[4];

    // ldg one x chunk (64 rows x 64 cols fp32) into regs: 2 c8-chunks/thread
    auto ldg_x = [&](int kt) {
        #pragma unroll
        for (int i = 0; i < 2; i++) {
            int idx = tid + i * 256;
            int row = idx >> 3, c8 = idx & 7;
            const float* src = x + (size_t)(rowbase + row) * Cc + kt * 64 + c8 * 8;
            xr[2 * i]     = *(const float4*)(src);
            xr[2 * i + 1] = *(const float4*)(src + 4);
        }
    };
    auto sts_x = [&](int buf) {
        #pragma unroll
        for (int i = 0; i < 2; i++) {
            int idx = tid + i * 256;
            int row = idx >> 3, c8 = idx & 7;
            __half2 h0 = __floats2half2_rn(xr[2*i].x,   xr[2*i].y);
            __half2 h1 = __floats2half2_rn(xr[2*i].z,   xr[2*i].w);
            __half2 h2 = __floats2half2_rn(xr[2*i+1].x, xr[2*i+1].y);
            __half2 h3 = __floats2half2_rn(xr[2*i+1].z, xr[2*i+1].w);
            uint4 u = make_uint4(*(uint32_t*)&h0, *(uint32_t*)&h1,
                                 *(uint32_t*)&h2, *(uint32_t*)&h3);
            *(uint4*)(S + xs_base(buf) + swz(row, c8)) = u;
        }
    };
    // W chunk via cp.async: 192 n-rows x 64 k halfs = 1536 16B chunks
    auto issue_W = [&](int kt, int buf) {
        #pragma unroll
        for (int i = 0; i < 6; i++) {
            int idx = tid + i * 256;
            int n = idx >> 3, c8 = idx & 7;          // n in 0..191
            int m = n >> 6, nn = n & 63;
            const __half* src = g_Wth + (size_t)m * 65536 + (size_t)nn * Cc + kt * 64 + c8 * 8;
            CP16(sb + ws_base(buf) + swz(n, c8), src);
        }
    };

    float acc[12][4];
    #pragma unroll
    for (int t = 0; t < 12; t++)
        #pragma unroll
        for (int e = 0; e < 4; e++) acc[t][e] = 0.f;

    // prologue
    ldg_x(0);
    sts_x(0);
    issue_W(0, 0);
    CP_COMMIT();
    CP_WAIT0();
    __syncthreads();

    for (int kt = 0; kt < 16; kt++) {
        const int cur = kt & 1, nxt = cur ^ 1;
        if (kt < 15) { ldg_x(kt + 1); issue_W(kt + 1, nxt); CP_COMMIT(); }

        #pragma unroll
        for (int ks = 0; ks < 4; ks++) {
            uint32_t xa[4];
            ldsm_x4(xa[0], xa[1], xa[2], xa[3],
                    sb + xs_base(cur) + swz(16 * rg + (lane & 15), 2 * ks + (lane >> 4)));
            #pragma unroll
            for (int g = 0; g < 6; g++) {
                uint32_t b0, b1, b2, b3;
                int row = 96 * cg + 16 * g + (lane & 7) + ((lane >> 4) << 3);
                int c8  = 2 * ks + ((lane >> 3) & 1);
                ldsm_x4(b0, b1, b2, b3, sb + ws_base(cur) + swz(row, c8));
                uint32_t bb0[2] = {b0, b1}, bb1[2] = {b2, b3};
                mma16816(acc[2 * g],     xa, bb0);
                mma16816(acc[2 * g + 1], xa, bb1);
            }
        }

        if (kt < 15) {
            __syncthreads();
            sts_x(nxt);
            CP_WAIT0();
            __syncthreads();
        }
    }

    // epilogue
    const int rl = lane >> 2;
    const int cq = 2 * (lane & 3);
    #pragma unroll
    for (int t = 0; t < 12; t++) {
        int n_global = 96 * cg + 8 * t;
        int m = n_global >> 6, col = (n_global & 63) + cq;
        __half* dst = (m == 0) ? g_Qh : (m == 1) ? g_Kh : g_Vh;
        float sc = (m == 0) ? QSCALE : 1.0f;
        size_t r0 = (size_t)(rowbase + 16 * rg + rl) * Hc + col;
        __half2 h0 = __floats2half2_rn(acc[t][0] * sc, acc[t][1] * sc);
        __half2 h1 = __floats2half2_rn(acc[t][2] * sc, acc[t][3] * sc);
        *(__half2*)&dst[r0]          = h0;
        *(__half2*)&dst[r0 + 8 * Hc] = h1;
    }
}

// ---------------------------------------------------------------------------
// attn_part: R10-winning configuration (2-way j-parity split).
// grid (32,8): a = x>>1, par = x&1.
// pass0: qt=a, j===par (mod 2);  pass1: qt=31-a, j===par^1 (mod 2).
// Every CTA does exactly 16 or 17 iterations; 256 CTAs -> 2 CTAs/SM.
// Writes unnormalized (O, l) partials to slot `par` (plain stores).
// ---------------------------------------------------------------------------
__global__ __launch_bounds__(128) void attn_part(void)
{
    __shared__ __align__(128) char S[40960];   // QS 8K | KS 2x8K | VS 2x8K
    const uint32_t sb = smem_u32(S);
    const uint32_t QS = 0, KS = 8192, VS = 24576;

    const int tid = threadIdx.x;
    const int wid = tid >> 5, lane = tid & 31;
    const int m0 = wid * 16;
    const int a   = blockIdx.x >> 1;
    const int par = blockIdx.x & 1;
    const int b = blockIdx.y;

    const __half* Qg = g_Qh + (size_t)b * Tc * Hc;
    const __half* Kg = g_Kh + (size_t)b * Tc * Hc;
    const __half* Vg = g_Vh + (size_t)b * Tc * Hc;

    auto issue_kv = [&](int j, int buf) {
        #pragma unroll
        for (int i = 0; i < 4; i++) {
            int idx = tid + i * 128;
            int row = idx >> 3, c8 = idx & 7;
            CP16(sb + KS + buf * 8192 + swz(row, c8),
                 Kg + (size_t)(j * 64 + row) * Hc + c8 * 8);
            CP16(sb + VS + buf * 8192 + swz(row, c8),
                 Vg + (size_t)(j * 64 + row) * Hc + c8 * 8);
        }
    };

    for (int pass = 0; pass < 2; pass++) {
        const int qt = pass ? (31 - a) : a;
        const int j0 = pass ? (par ^ 1) : par;
        const int qbase = qt * 64;

        __syncthreads();   // prior pass fully done before smem reuse

        // Q tile (fp16, 8KB) + first KV tile
        #pragma unroll
        for (int i = 0; i < 4; i++) {
            int idx = tid + i * 128;
            int row = idx >> 3, c8 = idx & 7;
            CP16(sb + QS + swz(row, c8), Qg + (size_t)(qbase + row) * Hc + c8 * 8);
        }
        CP_COMMIT();
        if (j0 <= qt) { issue_kv(j0, 0); CP_COMMIT(); }
        CP_WAIT0();
        __syncthreads();

        uint32_t qa[4][4];
        #pragma unroll
        for (int ks = 0; ks < 4; ks++) {
            ldsm_x4(qa[ks][0], qa[ks][1], qa[ks][2], qa[ks][3],
                    sb + QS + swz(m0 + (lane & 15), 2 * ks + (lane >> 4)));
        }

        float od[8][4];
        #pragma unroll
        for (int t = 0; t < 8; t++)
            #pragma unroll
            for (int e = 0; e < 4; e++) od[t][e] = 0.f;
        float l_lo = 0.f, l_hi = 0.f;

        int it = 0;
        for (int j = j0; j <= qt; j += 2, it++) {
            const int bf = it & 1;
            if (j + 2 <= qt) { issue_kv(j + 2, bf ^ 1); CP_COMMIT(); }

            // ---- S = Q K^T ----
            float sd[8][4];
            #pragma unroll
            for (int t = 0; t < 8; t++)
                #pragma unroll
                for (int e = 0; e < 4; e++) sd[t][e] = 0.f;

            #pragma unroll
            for (int ks = 0; ks < 4; ks++) {
                #pragma unroll
                for (int g = 0; g < 4; g++) {
                    uint32_t b0, b1, b2, b3;
                    int row = 16 * g + (lane & 7) + ((lane >> 4) << 3);
                    int c8  = 2 * ks + ((lane >> 3) & 1);
                    ldsm_x4(b0, b1, b2, b3, sb + KS + bf * 8192 + swz(row, c8));
                    uint32_t bb0[2] = {b0, b1}, bb1[2] = {b2, b3};
                    mma16816(sd[2 * g],     qa[ks], bb0);
                    mma16816(sd[2 * g + 1], qa[ks], bb1);
                }
            }

            // ---- p = 2^s (no max; logits bounded) ----
            const bool diag = (j == qt);
            const int rl = m0 + (lane >> 2), rh = rl + 8;
            #pragma unroll
            for (int t = 0; t < 8; t++) {
                int c0 = 8 * t + 2 * (lane & 3), c1 = c0 + 1;
                float e00 = fexp2(sd[t][0]);
                float e01 = fexp2(sd[t][1]);
                float e10 = fexp2(sd[t][2]);
                float e11 = fexp2(sd[t][3]);
                if (diag) {
                    if (c0 > rl) e00 = 0.f;
                    if (c1 > rl) e01 = 0.f;
                    if (c0 > rh) e10 = 0.f;
                    if (c1 > rh) e11 = 0.f;
                }
                l_lo += e00 + e01;
                l_hi += e10 + e11;
                sd[t][0] = e00; sd[t][1] = e01; sd[t][2] = e10; sd[t][3] = e11;
            }

            // ---- O += P V ----
            #pragma unroll
            for (int kk = 0; kk < 4; kk++) {
                uint32_t pa[4];
                __half2 p0 = __floats2half2_rn(sd[2*kk][0],   sd[2*kk][1]);
                __half2 p1 = __floats2half2_rn(sd[2*kk][2],   sd[2*kk][3]);
                __half2 p2 = __floats2half2_rn(sd[2*kk+1][0], sd[2*kk+1][1]);
                __half2 p3 = __floats2half2_rn(sd[2*kk+1][2], sd[2*kk+1][3]);
                pa[0] = *(uint32_t*)&p0; pa[1] = *(uint32_t*)&p1;
                pa[2] = *(uint32_t*)&p2; pa[3] = *(uint32_t*)&p3;

                #pragma unroll
                for (int g = 0; g < 4; g++) {
                    uint32_t b0, b1, b2, b3;
                    int row = 16 * kk + (lane & 7) + (((lane >> 3) & 1) << 3);
                    int c8  = 2 * g + (lane >> 4);
                    ldsm_x4_t(b0, b1, b2, b3, sb + VS + bf * 8192 + swz(row, c8));
                    uint32_t bb0[2] = {b0, b1}, bb1[2] = {b2, b3};
                    mma16816(od[2 * g],     pa, bb0);
                    mma16816(od[2 * g + 1], pa, bb1);
                }
            }

            if (j + 2 <= qt) { CP_WAIT0(); __syncthreads(); }
        }

        // ---- partial l (quad reduce) + partial store (plain STG) ----
        l_lo += __shfl_xor_sync(0xffffffffu, l_lo, 1);
        l_lo += __shfl_xor_sync(0xffffffffu, l_lo, 2);
        l_hi += __shfl_xor_sync(0xffffffffu, l_hi, 1);
        l_hi += __shfl_xor_sync(0xffffffffu, l_hi, 2);

        const int rl = m0 + (lane >> 2);
        float* pbase = &g_Po[par][((size_t)b * Tc + qbase + rl) * Hc];
        #pragma unroll
        for (int t = 0; t < 8; t++) {
            int col = 8 * t + 2 * (lane & 3);
            *(float2*)&pbase[col]          = make_float2(od[t][0], od[t][1]);
            *(float2*)&pbase[8 * Hc + col] = make_float2(od[t][2], od[t][3]);
        }
        if ((lane & 3) == 0) {
            g_Pl[par][(size_t)b * Tc + qbase + rl]     = l_lo;
            g_Pl[par][(size_t)b * Tc + qbase + rl + 8] = l_hi;
        }
    }
}

// ---------------------------------------------------------------------------
// merge: out = (O0 + O1) / (l0 + l1).  262144 threads (1024 x 256), one
// float4 out per thread.
// ---------------------------------------------------------------------------
__global__ __launch_bounds__(256) void merge_kernel(float* __restrict__ out)
{
    int gid = blockIdx.x * 256 + threadIdx.x;   // 0..262143
    int row = gid >> 4, c = (gid & 15) << 2;    // 16384 rows x 16 float4 cols
    float inv = 1.0f / (g_Pl[0][row] + g_Pl[1][row]);
    const size_t base = (size_t)row * Hc + c;
    float4 v0 = *(const float4*)&g_Po[0][base];
    float4 v1 = *(const float4*)&g_Po[1][base];
    *(float4*)&out[base] = make_float4((v0.x + v1.x) * inv, (v0.y + v1.y) * inv,
                                       (v0.z + v1.z) * inv, (v0.w + v1.w) * inv);
}

// ---------------------------------------------------------------------------
extern "C" void kernel_launch(void* const* d_in, const int* in_sizes, int n_in,
                              void* d_out, int out_size)
{
    const float* x  = (const float*)d_in[0];
    const float* Wq = (const float*)d_in[1];
    const float* Wk = (const float*)d_in[2];
    const float* Wv = (const float*)d_in[3];
    float* out = (float*)d_out;

    prep_W<<<192, 256>>>(Wq, Wk, Wv);

    cudaFuncSetAttribute(proj_kernel, cudaFuncAttributeMaxDynamicSharedMemorySize, 65536);
    proj_kernel<<<256, 256, 65536>>>(x);

    attn_part<<<dim3(32, 8), 128>>>();
    merge_kernel<<<1024, 256>>>(out);
}

// round 17
// speedup vs baseline: 1.0594x; 1.0594x over previous
#include <cuda_runtime.h>
#include <cuda_fp16.h>
#include <cstdint>

#define Bc 8
#define Tc 2048
#define Cc 1024
#define Hc 64
// (1/sqrt(1024)) * log2(e)  — folded into Q so softmax uses pure 2^x
#define QSCALE 0.045084220027840225f

// fp16 scratch
__device__ __half g_Qh[Bc * Tc * Hc];
__device__ __half g_Kh[Bc * Tc * Hc];
__device__ __half g_Vh[Bc * Tc * Hc];
__device__ __half g_Wth[3 * Hc * Cc];   // W transposed: [m][n][k]
// split-K partials (every element rewritten each launch — no zeroing needed)
__device__ float g_Po[2][Bc * Tc * Hc];
__device__ float g_Pl[2][Bc * Tc];

// ---------------------------------------------------------------------------
// helpers (generic PTX only: sm_80-class instructions)
// ---------------------------------------------------------------------------
__device__ __forceinline__ uint32_t smem_u32(const void* p) {
    uint32_t a;
    asm("{ .reg .u64 t; cvta.to.shared.u64 t, %1; cvt.u32.u64 %0, t; }" : "=r"(a) : "l"(p));
    return a;
}

__device__ __forceinline__ void ldsm_x4(uint32_t& r0, uint32_t& r1, uint32_t& r2,
                                        uint32_t& r3, uint32_t a) {
    asm volatile("ldmatrix.sync.aligned.m8n8.x4.shared.b16 {%0,%1,%2,%3}, [%4];"
                 : "=r"(r0), "=r"(r1), "=r"(r2), "=r"(r3) : "r"(a));
}
__device__ __forceinline__ void ldsm_x4_t(uint32_t& r0, uint32_t& r1, uint32_t& r2,
                                          uint32_t& r3, uint32_t a) {
    asm volatile("ldmatrix.sync.aligned.m8n8.x4.trans.shared.b16 {%0,%1,%2,%3}, [%4];"
                 : "=r"(r0), "=r"(r1), "=r"(r2), "=r"(r3) : "r"(a));
}

__device__ __forceinline__ void mma16816(float* d, const uint32_t* a,
                                         const uint32_t* b) {
    asm volatile(
        "mma.sync.aligned.m16n8k16.row.col.f32.f16.f16.f32 "
        "{%0,%1,%2,%3}, {%4,%5,%6,%7}, {%8,%9}, {%0,%1,%2,%3};"
        : "+f"(d[0]), "+f"(d[1]), "+f"(d[2]), "+f"(d[3])
        : "r"(a[0]), "r"(a[1]), "r"(a[2]), "r"(a[3]), "r"(b[0]), "r"(b[1]));
}

#define CP16(dst, src) asm volatile("cp.async.ca.shared.global [%0], [%1], 16;" :: "r"(dst), "l"(src))
#define CP_COMMIT()    asm volatile("cp.async.commit_group;" ::: "memory")
#define CP_WAIT0()     asm volatile("cp.async.wait_group 0;" ::: "memory")
#define CP_WAIT1()     asm volatile("cp.async.wait_group 1;" ::: "memory")

// swizzled byte offset in a [rows][64 halfs] fp16 tile (pitch 128B, 16B chunks)
__device__ __forceinline__ uint32_t swz(int row, int c8) {
    return (uint32_t)(row * 128 + ((c8 ^ (row & 7)) << 4));
}

// 2^y on the MUFU pipe (single EX2; rt_SMSP=8 -> 16 lanes/cyc/SM, ~4us chip
// for all 16.8M exps).  Replaces the 9-op FFMA polynomial that competed with
// the MMA/issue path.
__device__ __forceinline__ float fexp2(float y) {
    float r;
    asm("ex2.approx.f32 %0, %1;" : "=f"(r) : "f"(y));
    return r;
}

// ---------------------------------------------------------------------------
// prep: W [1024,64] fp32 -> Wt [3][64][1024] fp16 (coalesced float4 reads)
// ---------------------------------------------------------------------------
__global__ __launch_bounds__(256) void prep_W(const float* __restrict__ Wq,
                                              const float* __restrict__ Wk,
                                              const float* __restrict__ Wv)
{
    int j = blockIdx.x * 256 + threadIdx.x;     // float4 index
    int m = j >> 14, f = j & 16383;
    int k = f >> 4, n4 = (f & 15) << 2;
    const float* W = (m == 0) ? Wq : (m == 1) ? Wk : Wv;
    float4 v = *(const float4*)&W[(size_t)k * Hc + n4];
    __half* dst = g_Wth + (size_t)m * 65536 + (size_t)n4 * Cc + k;
    dst[0]        = __float2half(v.x);
    dst[Cc]       = __float2half(v.y);
    dst[2 * Cc]   = __float2half(v.z);
    dst[3 * Cc]   = __float2half(v.w);
}

// ---------------------------------------------------------------------------
// proj: fused QKV (R3 verbatim).  CTA = 128 rows x (3 x 64) cols, 256 threads.
// smem: XS[2] 16KB fp16 + WS[2] 24KB fp16 = 80KB dynamic.
// ---------------------------------------------------------------------------
__global__ __launch_bounds__(256) void proj_kernel(const float* __restrict__ x)
{
    extern __shared__ __align__(128) char S[];
    const uint32_t sb = smem_u32(S);

    const int tid = threadIdx.x;
    const int wid = tid >> 5, lane = tid & 31;
    const int m0 = wid * 16;
    const int rowbase = blockIdx.x * 128;

    auto xs_base = [&](int buf) { return (uint32_t)(buf * 16384); };
    auto ws_base = [&](int buf) { return (uint32_t)(32768 + buf * 24576); };

    float4 xr[8];

    auto ldg_x = [&](int kt) {
        #pragma unroll
        for (int i = 0; i < 4; i++) {
            int idx = tid + i * 256;
            int row = idx >> 3, c8 = idx & 7;
            const float* src = x + (size_t)(rowbase + row) * Cc + kt * 64 + c8 * 8;
            xr[2 * i]     = *(const float4*)(src);
            xr[2 * i + 1] = *(const float4*)(src + 4);
        }
    };
    auto sts_x = [&](int buf) {
        #pragma unroll
        for (int i = 0; i < 4; i++) {
            int idx = tid + i * 256;
            int row = idx >> 3, c8 = idx & 7;
            __half2 h0 = __floats2half2_rn(xr[2*i].x,   xr[2*i].y);
            __half2 h1 = __floats2half2_rn(xr[2*i].z,   xr[2*i].w);
            __half2 h2 = __floats2half2_rn(xr[2*i+1].x, xr[2*i+1].y);
            __half2 h3 = __floats2half2_rn(xr[2*i+1].z, xr[2*i+1].w);
            uint4 u = make_uint4(*(uint32_t*)&h0, *(uint32_t*)&h1,
                                 *(uint32_t*)&h2, *(uint32_t*)&h3);
            *(uint4*)(S + xs_base(buf) + swz(row, c8)) = u;
        }
    };
    auto issue_W = [&](int kt, int buf) {
        #pragma unroll
        for (int i = 0; i < 6; i++) {
            int idx = tid + i * 256;
            int m = idx >> 9, rem = idx & 511, n = rem >> 3, c8 = rem & 7;
            const __half* src = g_Wth + m * 65536 + n * Cc + kt * 64 + c8 * 8;
            CP16(sb + ws_base(buf) + m * 8192 + swz(n, c8), src);
        }
    };

    float acc[24][4];
    #pragma unroll
    for (int t = 0; t < 24; t++)
        #pragma unroll
        for (int e = 0; e < 4; e++) acc[t][e] = 0.f;

    ldg_x(0);
    sts_x(0);
    issue_W(0, 0);
    CP_COMMIT();
    CP_WAIT0();
    __syncthreads();

    for (int kt = 0; kt < 16; kt++) {
        const int cur = kt & 1, nxt = cur ^ 1;
        if (kt < 15) { ldg_x(kt + 1); issue_W(kt + 1, nxt); CP_COMMIT(); }

        #pragma unroll
        for (int ks = 0; ks < 4; ks++) {
            uint32_t xa[4];
            ldsm_x4(xa[0], xa[1], xa[2], xa[3],
                    sb + xs_base(cur) + swz(m0 + (lane & 15), 2 * ks + (lane >> 4)));
            #pragma unroll
            for (int m = 0; m < 3; m++) {
                #pragma unroll
                for (int g = 0; g < 4; g++) {
                    uint32_t b0, b1, b2, b3;
                    int row = 16 * g + (lane & 7) + ((lane >> 4) << 3);
                    int c8  = 2 * ks + ((lane >> 3) & 1);
                    ldsm_x4(b0, b1, b2, b3, sb + ws_base(cur) + m * 8192 + swz(row, c8));
                    uint32_t bb0[2] = {b0, b1}, bb1[2] = {b2, b3};
                    mma16816(acc[m * 8 + 2 * g],     xa, bb0);
                    mma16816(acc[m * 8 + 2 * g + 1], xa, bb1);
                }
            }
        }

        if (kt < 15) {
            __syncthreads();
            sts_x(nxt);
            CP_WAIT0();
            __syncthreads();
        }
    }

    const int rl = lane >> 2;
    const int cq = 2 * (lane & 3);
    #pragma unroll
    for (int t = 0; t < 24; t++) {
        int m = t >> 3, nt = t & 7;
        __half* dst = (m == 0) ? g_Qh : (m == 1) ? g_Kh : g_Vh;
        float sc = (m == 0) ? QSCALE : 1.0f;
        int col = 8 * nt + cq;
        size_t r0 = (size_t)(rowbase + m0 + rl) * Hc + col;
        __half2 h0 = __floats2half2_rn(acc[t][0] * sc, acc[t][1] * sc);
        __half2 h1 = __floats2half2_rn(acc[t][2] * sc, acc[t][3] * sc);
        *(__half2*)&dst[r0]           = h0;
        *(__half2*)&dst[r0 + 8 * Hc]  = h1;
    }
}

// ---------------------------------------------------------------------------
// attn_part: R10-winning configuration (2-way j-parity split).
// grid (32,8): a = x>>1, par = x&1.
// pass0: qt=a, j===par (mod 2);  pass1: qt=31-a, j===par^1 (mod 2).
// Every CTA does exactly 16 or 17 iterations; 256 CTAs -> 2 CTAs/SM.
// Writes unnormalized (O, l) partials to slot `par` (plain stores).
// ---------------------------------------------------------------------------
__global__ __launch_bounds__(128) void attn_part(void)
{
    __shared__ __align__(128) char S[40960];   // QS 8K | KS 2x8K | VS 2x8K
    const uint32_t sb = smem_u32(S);
    const uint32_t QS = 0, KS = 8192, VS = 24576;

    const int tid = threadIdx.x;
    const int wid = tid >> 5, lane = tid & 31;
    const int m0 = wid * 16;
    const int a   = blockIdx.x >> 1;
    const int par = blockIdx.x & 1;
    const int b = blockIdx.y;

    const __half* Qg = g_Qh + (size_t)b * Tc * Hc;
    const __half* Kg = g_Kh + (size_t)b * Tc * Hc;
    const __half* Vg = g_Vh + (size_t)b * Tc * Hc;

    auto issue_kv = [&](int j, int buf) {
        #pragma unroll
        for (int i = 0; i < 4; i++) {
            int idx = tid + i * 128;
            int row = idx >> 3, c8 = idx & 7;
            CP16(sb + KS + buf * 8192 + swz(row, c8),
                 Kg + (size_t)(j * 64 + row) * Hc + c8 * 8);
            CP16(sb + VS + buf * 8192 + swz(row, c8),
                 Vg + (size_t)(j * 64 + row) * Hc + c8 * 8);
        }
    };

    for (int pass = 0; pass < 2; pass++) {
        const int qt = pass ? (31 - a) : a;
        const int j0 = pass ? (par ^ 1) : par;
        const int qbase = qt * 64;

        __syncthreads();   // prior pass fully done before smem reuse

        // Q tile (fp16, 8KB) + first KV tile
        #pragma unroll
        for (int i = 0; i < 4; i++) {
            int idx = tid + i * 128;
            int row = idx >> 3, c8 = idx & 7;
            CP16(sb + QS + swz(row, c8), Qg + (size_t)(qbase + row) * Hc + c8 * 8);
        }
        CP_COMMIT();
        if (j0 <= qt) { issue_kv(j0, 0); CP_COMMIT(); }
        CP_WAIT0();
        __syncthreads();

        uint32_t qa[4][4];
        #pragma unroll
        for (int ks = 0; ks < 4; ks++) {
            ldsm_x4(qa[ks][0], qa[ks][1], qa[ks][2], qa[ks][3],
                    sb + QS + swz(m0 + (lane & 15), 2 * ks + (lane >> 4)));
        }

        float od[8][4];
        #pragma unroll
        for (int t = 0; t < 8; t++)
            #pragma unroll
            for (int e = 0; e < 4; e++) od[t][e] = 0.f;
        float l_lo = 0.f, l_hi = 0.f;

        int it = 0;
        for (int j = j0; j <= qt; j += 2, it++) {
            const int bf = it & 1;
            if (j + 2 <= qt) { issue_kv(j + 2, bf ^ 1); CP_COMMIT(); }

            // ---- S = Q K^T ----
            float sd[8][4];
            #pragma unroll
            for (int t = 0; t < 8; t++)
                #pragma unroll
                for (int e = 0; e < 4; e++) sd[t][e] = 0.f;

            #pragma unroll
            for (int ks = 0; ks < 4; ks++) {
                #pragma unroll
                for (int g = 0; g < 4; g++) {
                    uint32_t b0, b1, b2, b3;
                    int row = 16 * g + (lane & 7) + ((lane >> 4) << 3);
                    int c8  = 2 * ks + ((lane >> 3) & 1);
                    ldsm_x4(b0, b1, b2, b3, sb + KS + bf * 8192 + swz(row, c8));
                    uint32_t bb0[2] = {b0, b1}, bb1[2] = {b2, b3};
                    mma16816(sd[2 * g],     qa[ks], bb0);
                    mma16816(sd[2 * g + 1], qa[ks], bb1);
                }
            }

            // ---- p = 2^s (MUFU EX2; no max — logits bounded) ----
            const bool diag = (j == qt);
            const int rl = m0 + (lane >> 2), rh = rl + 8;
            #pragma unroll
            for (int t = 0; t < 8; t++) {
                int c0 = 8 * t + 2 * (lane & 3), c1 = c0 + 1;
                float e00 = fexp2(sd[t][0]);
                float e01 = fexp2(sd[t][1]);
                float e10 = fexp2(sd[t][2]);
                float e11 = fexp2(sd[t][3]);
                if (diag) {
                    if (c0 > rl) e00 = 0.f;
                    if (c1 > rl) e01 = 0.f;
                    if (c0 > rh) e10 = 0.f;
                    if (c1 > rh) e11 = 0.f;
                }
                l_lo += e00 + e01;
                l_hi += e10 + e11;
                sd[t][0] = e00; sd[t][1] = e01; sd[t][2] = e10; sd[t][3] = e11;
            }

            // ---- O += P V ----
            #pragma unroll
            for (int kk = 0; kk < 4; kk++) {
                uint32_t pa[4];
                __half2 p0 = __floats2half2_rn(sd[2*kk][0],   sd[2*kk][1]);
                __half2 p1 = __floats2half2_rn(sd[2*kk][2],   sd[2*kk][3]);
                __half2 p2 = __floats2half2_rn(sd[2*kk+1][0], sd[2*kk+1][1]);
                __half2 p3 = __floats2half2_rn(sd[2*kk+1][2], sd[2*kk+1][3]);
                pa[0] = *(uint32_t*)&p0; pa[1] = *(uint32_t*)&p1;
                pa[2] = *(uint32_t*)&p2; pa[3] = *(uint32_t*)&p3;

                #pragma unroll
                for (int g = 0; g < 4; g++) {
                    uint32_t b0, b1, b2, b3;
                    int row = 16 * kk + (lane & 7) + (((lane >> 3) & 1) << 3);
                    int c8  = 2 * g + (lane >> 4);
                    ldsm_x4_t(b0, b1, b2, b3, sb + VS + bf * 8192 + swz(row, c8));
                    uint32_t bb0[2] = {b0, b1}, bb1[2] = {b2, b3};
                    mma16816(od[2 * g],     pa, bb0);
                    mma16816(od[2 * g + 1], pa, bb1);
                }
            }

            if (j + 2 <= qt) { CP_WAIT0(); __syncthreads(); }
        }

        // ---- partial l (quad reduce) + partial store (plain STG) ----
        l_lo += __shfl_xor_sync(0xffffffffu, l_lo, 1);
        l_lo += __shfl_xor_sync(0xffffffffu, l_lo, 2);
        l_hi += __shfl_xor_sync(0xffffffffu, l_hi, 1);
        l_hi += __shfl_xor_sync(0xffffffffu, l_hi, 2);

        const int rl = m0 + (lane >> 2);
        float* pbase = &g_Po[par][((size_t)b * Tc + qbase + rl) * Hc];
        #pragma unroll
        for (int t = 0; t < 8; t++) {
            int col = 8 * t + 2 * (lane & 3);
            *(float2*)&pbase[col]          = make_float2(od[t][0], od[t][1]);
            *(float2*)&pbase[8 * Hc + col] = make_float2(od[t][2], od[t][3]);
        }
        if ((lane & 3) == 0) {
            g_Pl[par][(size_t)b * Tc + qbase + rl]     = l_lo;
            g_Pl[par][(size_t)b * Tc + qbase + rl + 8] = l_hi;
        }
    }
}

// ---------------------------------------------------------------------------
// merge: out = (O0 + O1) / (l0 + l1).  262144 threads (1024 x 256), one
// float4 out per thread.
// ---------------------------------------------------------------------------
__global__ __launch_bounds__(256) void merge_kernel(float* __restrict__ out)
{
    int gid = blockIdx.x * 256 + threadIdx.x;   // 0..262143
    int row = gid >> 4, c = (gid & 15) << 2;    // 16384 rows x 16 float4 cols
    float inv = 1.0f / (g_Pl[0][row] + g_Pl[1][row]);
    const size_t base = (size_t)row * Hc + c;
    float4 v0 = *(const float4*)&g_Po[0][base];
    float4 v1 = *(const float4*)&g_Po[1][base];
    *(float4*)&out[base] = make_float4((v0.x + v1.x) * inv, (v0.y + v1.y) * inv,
                                       (v0.z + v1.z) * inv, (v0.w + v1.w) * inv);
}

// ---------------------------------------------------------------------------
extern "C" void kernel_launch(void* const* d_in, const int* in_sizes, int n_in,
                              void* d_out, int out_size)
{
    const float* x  = (const float*)d_in[0];
    const float* Wq = (const float*)d_in[1];
    const float* Wk = (const float*)d_in[2];
    const float* Wv = (const float*)d_in[3];
    float* out = (float*)d_out;

    prep_W<<<192, 256>>>(Wq, Wk, Wv);

    cudaFuncSetAttribute(proj_kernel, cudaFuncAttributeMaxDynamicSharedMemorySize, 81920);
    proj_kernel<<<128, 256, 81920>>>(x);

    attn_part<<<dim3(32, 8), 128>>>();
    merge_kernel<<<1024, 256>>>(out);
}